// round 11
// baseline (speedup 1.0000x reference)
#include <cuda_runtime.h>

#define D       64
#define K       1024
#define KC      128        // codes per shared-memory chunk
#define TPB     128
#define PIX     2          // pixels per thread
#define NSLICE  4          // codebook slices (256 codes each)
#define SLICE_K (K / NSLICE)

__device__ float              g_cnorm[K];              // ||e_k||^2
__device__ unsigned long long g_part[NSLICE][65536];   // per-slice best (dist,idx)

__global__ void cnorm_kernel(const float* __restrict__ e)
{
    int k = blockIdx.x * blockDim.x + threadIdx.x;
    if (k < K) {
        float s = 0.0f;
        #pragma unroll
        for (int i = 0; i < D; ++i) {
            float v = e[i * K + k];
            s = fmaf(v, v, s);
        }
        g_cnorm[k] = s;
    }
}

#define FMA2(acc, a, b) \
    asm("fma.rn.f32x2 %0, %1, %2, %0;" : "+l"(acc) : "l"(a), "l"(b))

// Order-preserving float->uint: a < b  <=>  enc(a) < enc(b).
__device__ __forceinline__ unsigned enc_f32(float f)
{
    unsigned u = __float_as_uint(f);
    return u ^ (0x80000000u | (unsigned)(((int)u) >> 31));
}

// One (pixel-tile, codebook-slice) per block. 2 pixels/thread, 8-code groups.
// Regs capped at 170 -> 3 blocks/SM (3 warps/SMSP) to hide LDS latency by
// warp interleave instead of the register-hungry explicit pipeline.
__global__ __launch_bounds__(TPB, 3)
void vq_kernel(const float* __restrict__ x,
               const float* __restrict__ e)
{
    __shared__ __align__(16) float sE[D][KC];
    __shared__ float sC[KC];

    const int tid   = threadIdx.x;
    const int tile  = blockIdx.x;          // 256 pixel tiles
    const int slice = blockIdx.y;          // 4 codebook slices
    const int kbase = slice * SLICE_K;

    const int p0 = tile * (TPB * PIX) + tid;
    const int p1 = p0 + TPB;
    const int xbase0 = (p0 >> 12) * (D * 4096) + (p0 & 4095);
    const int xbase1 = (p1 >> 12) * (D * 4096) + (p1 & 4095);

    float xr0[D], xr1[D];
    #pragma unroll
    for (int c = 0; c < D; ++c) {
        xr0[c] = x[xbase0 + c * 4096];
        xr1[c] = x[xbase1 + c * 4096];
    }

    float best0 = 3.4e38f, best1 = 3.4e38f;
    int   bi0 = kbase,     bi1 = kbase;

    for (int k0 = kbase; k0 < kbase + SLICE_K; k0 += KC) {
        #pragma unroll
        for (int pass = 0; pass < (D * KC / 4) / TPB; ++pass) {
            int idx = pass * TPB + tid;
            int n   = idx >> 5;
            int c4  = idx & 31;
            float4 v = *reinterpret_cast<const float4*>(&e[n * K + k0 + c4 * 4]);
            *reinterpret_cast<float4*>(&sE[n][c4 * 4]) = v;
        }
        sC[tid] = g_cnorm[k0 + tid];
        __syncthreads();

        // 8 codes per group: 4 packed-pair accumulators per pixel.
        for (int kk = 0; kk < KC; kk += 8) {
            unsigned long long a0[4], a1[4];
            #pragma unroll
            for (int j = 0; j < 4; ++j) { a0[j] = 0ULL; a1[j] = 0ULL; }

            #pragma unroll 8
            for (int i = 0; i < D; ++i) {
                const ulonglong2* ep =
                    reinterpret_cast<const ulonglong2*>(&sE[i][kk]);
                ulonglong2 e0 = ep[0];
                ulonglong2 e1 = ep[1];
                unsigned long long xx0, xx1;
                asm("mov.b64 %0, {%1, %1};"
                    : "=l"(xx0) : "r"(__float_as_uint(xr0[i])));
                asm("mov.b64 %0, {%1, %1};"
                    : "=l"(xx1) : "r"(__float_as_uint(xr1[i])));
                FMA2(a0[0], xx0, e0.x);  FMA2(a1[0], xx1, e0.x);
                FMA2(a0[1], xx0, e0.y);  FMA2(a1[1], xx1, e0.y);
                FMA2(a0[2], xx0, e1.x);  FMA2(a1[2], xx1, e1.x);
                FMA2(a0[3], xx0, e1.y);  FMA2(a1[3], xx1, e1.y);
            }

            // dist = ||e||^2 - 2*(x.e); strict '<' ascending k => first index
            // wins ties within the slice (matches jnp.argmin).
            #pragma unroll
            for (int j = 0; j < 4; ++j) {
                float cA = sC[kk + 2 * j];
                float cB = sC[kk + 2 * j + 1];
                float d0, d1;
                asm("mov.b64 {%0, %1}, %2;" : "=f"(d0), "=f"(d1) : "l"(a0[j]));
                float s0 = fmaf(-2.0f, d0, cA);
                float s1 = fmaf(-2.0f, d1, cB);
                if (s0 < best0) { best0 = s0; bi0 = k0 + kk + 2 * j; }
                if (s1 < best0) { best0 = s1; bi0 = k0 + kk + 2 * j + 1; }
                asm("mov.b64 {%0, %1}, %2;" : "=f"(d0), "=f"(d1) : "l"(a1[j]));
                s0 = fmaf(-2.0f, d0, cA);
                s1 = fmaf(-2.0f, d1, cB);
                if (s0 < best1) { best1 = s0; bi1 = k0 + kk + 2 * j; }
                if (s1 < best1) { best1 = s1; bi1 = k0 + kk + 2 * j + 1; }
            }
        }
        __syncthreads();
    }

    // Pack (dist, idx); lexicographic u64 min across slices reproduces the
    // global tie rule (equal dist bits -> lower code index wins).
    g_part[slice][p0] = ((unsigned long long)enc_f32(best0) << 32) | (unsigned)bi0;
    g_part[slice][p1] = ((unsigned long long)enc_f32(best1) << 32) | (unsigned)bi1;
}

// Merge the 4 slice results and gather the winning code vectors.
__global__ __launch_bounds__(256)
void merge_gather_kernel(const float* __restrict__ e,
                         float* __restrict__ out)
{
    const int p = blockIdx.x * 256 + threadIdx.x;   // pixel id
    unsigned long long best = g_part[0][p];
    #pragma unroll
    for (int s = 1; s < NSLICE; ++s) {
        unsigned long long v = g_part[s][p];
        if (v < best) best = v;
    }
    const int idx   = (int)(best & 0xFFFFFFFFu);
    const int xbase = (p >> 12) * (D * 4096) + (p & 4095);
    #pragma unroll
    for (int c = 0; c < D; ++c)
        out[xbase + c * 4096] = __ldg(&e[c * K + idx]);
}

extern "C" void kernel_launch(void* const* d_in, const int* in_sizes, int n_in,
                              void* d_out, int out_size)
{
    const float* x = (const float*)d_in[0];
    const float* e = (const float*)d_in[1];
    if (n_in >= 2 && in_sizes[0] == D * K && in_sizes[1] == 16 * D * 64 * 64) {
        x = (const float*)d_in[1];
        e = (const float*)d_in[0];
    }
    float* out = (float*)d_out;

    cnorm_kernel<<<(K + 127) / 128, 128>>>(e);
    dim3 grid(65536 / (TPB * PIX), NSLICE);
    vq_kernel<<<grid, TPB>>>(x, e);
    merge_gather_kernel<<<65536 / 256, 256>>>(e, out);
}